// round 15
// baseline (speedup 1.0000x reference)
#include <cuda_runtime.h>
#include <cuda_bf16.h>
#include <cstdint>

// ---------------- problem constants ----------------
#define B_   256
#define K_   32
#define M_   64
#define MN_  256
#define E_   128
#define H_   128
#define Q_   128
#define NR_  500

// ---------------- scratch (device globals) ----------------
__device__ float g_pnode [B_ * H_];
__device__ float g_c0d   [B_ * K_];
__device__ float g_cd    [B_ * K_];
__device__ float g_state [B_ * H_];
__device__ float g_nWT   [(H_ + Q_) * H_];        // nexthop_W transposed
__device__ float g_init  [B_ * H_];
__device__ float g_upd   [B_ * K_ * H_];
__device__ float g_relsum[B_ * K_ * E_];
__device__ float g_zero  [H_];                    // stays zero
__device__ __align__(16) __nv_bfloat16 g_cWb  [H_ * 384];     // candidate_W bf16
__device__ __align__(16) __nv_bfloat16 g_hpWb [H_ * 256];     // [hidden_W | pass_W[:,128:]] bf16

__device__ __forceinline__ float lrelu(float x) { return x >= 0.f ? x : 0.01f * x; }

__device__ __forceinline__ uint32_t smem_u32(const void* p) {
    uint32_t a;
    asm("{ .reg .u64 t; cvta.to.shared.u64 t, %1; cvt.u32.u64 %0, t; }" : "=r"(a) : "l"(p));
    return a;
}
__device__ __forceinline__ void mma16816(float* c, const uint32_t* a, const uint32_t* b) {
    asm volatile(
        "mma.sync.aligned.m16n8k16.row.col.f32.bf16.bf16.f32 "
        "{%0,%1,%2,%3}, {%4,%5,%6,%7}, {%8,%9}, {%0,%1,%2,%3};"
        : "+f"(c[0]), "+f"(c[1]), "+f"(c[2]), "+f"(c[3])
        : "r"(a[0]), "r"(a[1]), "r"(a[2]), "r"(a[3]), "r"(b[0]), "r"(b[1]));
}
__device__ __forceinline__ void ldm_x4(uint32_t* r, uint32_t addr) {
    asm volatile("ldmatrix.sync.aligned.m8n8.x4.shared.b16 {%0,%1,%2,%3}, [%4];"
        : "=r"(r[0]), "=r"(r[1]), "=r"(r[2]), "=r"(r[3]) : "r"(addr));
}
__device__ __forceinline__ uint4 cvt8_bf16(float4 va, float4 vb) {
    __nv_bfloat162 p0 = __floats2bfloat162_rn(va.x, va.y);
    __nv_bfloat162 p1 = __floats2bfloat162_rn(va.z, va.w);
    __nv_bfloat162 p2 = __floats2bfloat162_rn(vb.x, vb.y);
    __nv_bfloat162 p3 = __floats2bfloat162_rn(vb.z, vb.w);
    uint4 u;
    u.x = *(uint32_t*)&p0; u.y = *(uint32_t*)&p1;
    u.z = *(uint32_t*)&p2; u.w = *(uint32_t*)&p3;
    return u;
}
#define CP16(dst, src) \
    asm volatile("cp.async.cg.shared.global [%0], [%1], 16;" :: "r"(dst), "l"(src) : "memory")
#define CPC()  asm volatile("cp.async.commit_group;" ::: "memory")
#define CPW0() asm volatile("cp.async.wait_group 0;" ::: "memory")

#define PITCH2 40   // 32 bf16 + 8 pad: rows at 80B -> distinct banks for ldmatrix

// ============================================================================
// Setup: blocks [0,448) weight prep | [448,704) init/pnode | [704,4800) relsum
// (byte-identical to R14 measured version)
// ============================================================================
__global__ __launch_bounds__(256)
void ksetup(const float* __restrict__ cW, const float* __restrict__ hW,
            const float* __restrict__ pW, const float* __restrict__ nW,
            const int* __restrict__ start, const float* __restrict__ ent,
            const float* __restrict__ hb,
            const int* __restrict__ nb_nodes, const int* __restrict__ nb_rels,
            const int* __restrict__ nb_num, const float* __restrict__ rel_emb)
{
    int blk = blockIdx.x, t = threadIdx.x;

    if (blk < 448) {
        int i = blk * 256 + t;
        if (i < 49152) {
            g_cWb[i] = __float2bfloat16(cW[i]);
        } else if (i < 81920) {
            int j = i - 49152;
            int n = j >> 8, k = j & 255;
            g_hpWb[j] = __float2bfloat16(k < 128 ? hW[n * 128 + k] : pW[n * 256 + k]);
        } else {
            int m = i - 81920;
            int e = m >> 7, n = m & 127;
            g_nWT[m] = nW[n * 256 + e];
        }
        return;
    }

    if (blk < 704) {
        int b = blk - 448;
        __shared__ float xs[E_], iv[H_];
        if (t < 128) xs[t] = ent[(long)start[b] * E_ + t];
        __syncthreads();
        if (t < 128) {
            float acc = 0.f;
            const float* wr = hW + t * E_;
            #pragma unroll 8
            for (int e = 0; e < E_; e++) acc += wr[e] * xs[e];
            float v = lrelu(acc + hb[t]);
            iv[t] = v;
            g_init[b * H_ + t] = v;
        }
        __syncthreads();
        if (t < 128) {
            float p = 0.f;
            const float* pr = pW + t * (H_ + E_);
            #pragma unroll 8
            for (int e = 0; e < H_; e++) p += pr[e] * iv[e];
            g_pnode[b * H_ + t] = p;
        }
        return;
    }

    {
        __shared__ int s_rel[2][M_];
        __shared__ int s_c0[2];
        int sub = t >> 7, tt = t & 127;
        int r = (blk - 704) * 2 + sub;
        if (tt == 0) s_c0[sub] = 0;
        int cnt = nb_num[r];
        if (cnt < 0)  cnt = 0;
        if (cnt > M_) cnt = M_;
        if (tt < M_) s_rel[sub][tt] = nb_rels[r * M_ + tt];
        __syncthreads();
        if (tt < cnt && nb_nodes[r * M_ + tt] == 0) atomicAdd(&s_c0[sub], 1);

        float acc = 0.f;
        int m = 0;
        for (; m + 4 <= cnt; m += 4) {
            float v0 = rel_emb[s_rel[sub][m + 0] * E_ + tt];
            float v1 = rel_emb[s_rel[sub][m + 1] * E_ + tt];
            float v2 = rel_emb[s_rel[sub][m + 2] * E_ + tt];
            float v3 = rel_emb[s_rel[sub][m + 3] * E_ + tt];
            acc += (v0 + v1) + (v2 + v3);
        }
        for (; m < cnt; m++) acc += rel_emb[s_rel[sub][m] * E_ + tt];
        __syncthreads();

        float denom = (cnt == 0) ? 1.f : (float)cnt;
        g_relsum[r * E_ + tt] = acc / denom;
        if (tt == 0) {
            g_c0d[r] = (float)s_c0[sub] / denom;
            g_cd[r]  = (float)cnt / denom;
        }
    }
}

// ============================================================================
// Kernel 3 (warp-mma bf16 + fused k4): upd GEMM, then per-block (2 batches):
//   cc=[cur;query], gate -> out[:,MN], state matvec (2-way e-split)
//   R=8192, N=128, K=256.  BM=64, grid(128), block(256)
// ============================================================================
__global__ __launch_bounds__(256)
void k3_upd(const int* __restrict__ aims, const float* __restrict__ ent,
            const float* __restrict__ hb, const float* __restrict__ pb,
            const int* __restrict__ currents, const float* __restrict__ query,
            const float* __restrict__ gW, const float* __restrict__ gb,
            const float* __restrict__ nbias, float* __restrict__ out)
{
    __shared__ __nv_bfloat16 As[2][64 * PITCH2];
    __shared__ __nv_bfloat16 Bs[2][128 * PITCH2];
    __shared__ const float* rowp[64];
    __shared__ float s_c0d[64], s_cd[64], s_hb[128], s_pb[128], s_pn[2 * 128];
    __shared__ float s_cc[256], s_part[2][128], s_red[128];

    int t    = threadIdx.x;
    int wid  = t >> 5, lane = t & 31;
    int l4   = lane >> 2, lp2 = (lane & 3) * 2;
    int wm   = wid & 1, wn = wid >> 1;
    int rr0  = blockIdx.x * 64;
    int b0   = rr0 >> 5;

    if (t < 64) {
        int rr = rr0 + t;
        rowp[t]  = ent + (long)aims[rr] * E_;
        s_c0d[t] = g_c0d[rr];
        s_cd[t]  = g_cd[rr];
    }
    if (t < 128) {
        s_hb[t] = hb[t];
        s_pb[t] = pb[t];
        s_pn[t] = g_pnode[b0 * H_ + t];
        s_pn[128 + t] = g_pnode[(b0 + 1) * H_ + t];
    }
    __syncthreads();

    int aRow  = t >> 2, aC0 = (t & 3) * 8;
    int bRow0 = t >> 2, bRow1 = 64 + (t >> 2);
    uint32_t bSm0 = (uint32_t)(bRow0 * PITCH2 + aC0) * 2;
    uint32_t bSm1 = (uint32_t)(bRow1 * PITCH2 + aC0) * 2;

    uint32_t a_off = (uint32_t)((wm * 32 + (lane & 15)) * PITCH2 + ((lane >> 4) << 3)) * 2;
    uint32_t b_off = (uint32_t)((wn * 32 + (lane & 7) + ((lane >> 4) << 3)) * PITCH2
                                + (((lane >> 3) & 1) << 3)) * 2;
    const uint32_t STEP16 = (uint32_t)(16 * PITCH2) * 2;

    float acc[32];
    #pragma unroll
    for (int i = 0; i < 32; i++) acc[i] = 0.f;

    // tile 0: A via regs, B via cp.async
    {
        const float* src = rowp[aRow] + aC0;
        uint4 a0 = cvt8_bf16(*(const float4*)src, *(const float4*)(src + 4));
        uint32_t bdst = smem_u32(Bs[0]);
        CP16(bdst + bSm0, g_hpWb + bRow0 * 256 + aC0);
        CP16(bdst + bSm1, g_hpWb + bRow1 * 256 + aC0);
        CPC();
        *(uint4*)(As[0] + aRow * PITCH2 + aC0) = a0;
        CPW0();
    }
    __syncthreads();

    uint4 aPf;
    #pragma unroll
    for (int j = 0; j < 8; j++) {
        int st = j & 1;
        if (j < 7) {
            int jn = j + 1;
            int kof = (jn & 3) * 32;
            const float* src = (jn < 4) ? (rowp[aRow] + kof + aC0)
                                        : (g_relsum + (rr0 + aRow) * E_ + kof + aC0);
            aPf = cvt8_bf16(*(const float4*)src, *(const float4*)(src + 4));
            uint32_t bdst = smem_u32(Bs[st ^ 1]);
            CP16(bdst + bSm0, g_hpWb + bRow0 * 256 + jn * 32 + aC0);
            CP16(bdst + bSm1, g_hpWb + bRow1 * 256 + jn * 32 + aC0);
            CPC();
        }
        uint32_t asb = smem_u32(As[st]), bsb = smem_u32(Bs[st]);
        #pragma unroll
        for (int ks = 0; ks < 2; ks++) {
            uint32_t kb = (uint32_t)(ks * 16) * 2;
            uint32_t a0[4], a1[4], b0[4], b1[4];
            ldm_x4(a0, asb + a_off + kb);
            ldm_x4(a1, asb + a_off + STEP16 + kb);
            ldm_x4(b0, bsb + b_off + kb);
            ldm_x4(b1, bsb + b_off + STEP16 + kb);
            mma16816(acc + 0,  a0, b0);  mma16816(acc + 4,  a0, b0 + 2);
            mma16816(acc + 8,  a0, b1);  mma16816(acc + 12, a0, b1 + 2);
            mma16816(acc + 16, a1, b0);  mma16816(acc + 20, a1, b0 + 2);
            mma16816(acc + 24, a1, b1);  mma16816(acc + 28, a1, b1 + 2);
        }
        if (j < 7) {
            *(uint4*)(As[st ^ 1] + aRow * PITCH2 + aC0) = aPf;
            CPW0();
            __syncthreads();
        }
    }

    // epilogue -> g_upd
    #pragma unroll
    for (int mi = 0; mi < 2; mi++) {
        int rl0 = wm * 32 + mi * 16 + l4, rl1 = rl0 + 8;
        int bi0 = (rl0 >> 5) * 128, bi1 = (rl1 >> 5) * 128;
        #pragma unroll
        for (int ni = 0; ni < 4; ni++) {
            int c0 = wn * 32 + ni * 8 + lp2, c1 = c0 + 1;
            const float* a = acc + mi * 16 + ni * 4;
            g_upd[(rr0 + rl0) * H_ + c0] =
                lrelu(a[0] + s_hb[c0] + s_c0d[rl0] * s_pn[bi0 + c0] + s_cd[rl0] * s_pb[c0]);
            g_upd[(rr0 + rl0) * H_ + c1] =
                lrelu(a[1] + s_hb[c1] + s_c0d[rl0] * s_pn[bi0 + c1] + s_cd[rl0] * s_pb[c1]);
            g_upd[(rr0 + rl1) * H_ + c0] =
                lrelu(a[2] + s_hb[c0] + s_c0d[rl1] * s_pn[bi1 + c0] + s_cd[rl1] * s_pb[c0]);
            g_upd[(rr0 + rl1) * H_ + c1] =
                lrelu(a[3] + s_hb[c1] + s_c0d[rl1] * s_pn[bi1 + c1] + s_cd[rl1] * s_pb[c1]);
        }
    }
    __syncthreads();   // g_upd (this block's 2 batches) now visible to all threads

    // ---------------- fused k4: for the 2 batches this block owns ----------------
    #pragma unroll
    for (int bl = 0; bl < 2; bl++) {
        int b = b0 + bl;
        if (t < 128) {
            int c = currents[b];
            float cur;
            if (c == 0)                 cur = g_init[b * H_ + t];
            else if (c >= 1 && c <= K_) cur = g_upd[(b * K_ + (c - 1)) * H_ + t];
            else                        cur = 0.f;
            float q = query[b * Q_ + t];
            s_cc[t]       = cur;
            s_cc[128 + t] = q;
            s_red[t] = gW[t] * cur + gW[128 + t] * q;
        }
        __syncthreads();
        for (int s = 64; s > 0; s >>= 1) {
            if (t < s) s_red[t] += s_red[t + s];
            __syncthreads();
        }
        if (t == 0) out[b * (MN_ + 1) + MN_] = s_red[0] + gb[0];

        // state matvec: 2-way e-split (n = t&127, seg = t>>7, 128 e's each)
        {
            int n = t & 127, seg = t >> 7;
            const float* w = g_nWT + (seg * 128) * 128 + n;
            float acc4 = 0.f;
            #pragma unroll 8
            for (int e = 0; e < 128; e++) acc4 += s_cc[seg * 128 + e] * w[e * 128];
            s_part[seg][n] = acc4;
        }
        __syncthreads();
        if (t < 128)
            g_state[b * H_ + t] = lrelu(s_part[0][t] + s_part[1][t] + nbias[t]);
        __syncthreads();   // protect s_cc/s_red/s_part before next bl iteration
    }
}

// ============================================================================
// Kernel 5 (warp-mma bf16, 32x32 warp tiles, cp.async B): candidate GEMM
//   R=65536, N=128, K=384.  BM=64, grid(1024), block(256) — R14-identical
// ============================================================================
__global__ __launch_bounds__(256)
void k5_cand(const int* __restrict__ cnodes, const int* __restrict__ cents,
             const int* __restrict__ crels, const int* __restrict__ cmask,
             const float* __restrict__ ent, const float* __restrict__ rel,
             const float* __restrict__ cb, float* __restrict__ out)
{
    __shared__ __nv_bfloat16 As[2][64 * PITCH2];
    __shared__ __nv_bfloat16 Bs[2][128 * PITCH2];
    __shared__ const float* pN[64];
    __shared__ const float* pE[64];
    __shared__ const float* pR[64];
    __shared__ float s_state[H_], s_cb[H_];
    __shared__ float sred[4][64];

    int t    = threadIdx.x;
    int wid  = t >> 5, lane = t & 31;
    int l4   = lane >> 2, lp2 = (lane & 3) * 2;
    int wm   = wid & 1, wn = wid >> 1;
    int rr0  = blockIdx.x * 64;
    int b    = rr0 >> 8;

    if (t < 64) {
        int rr = rr0 + t;
        int node = cnodes[rr];
        const float* p;
        if (node == 0)                    p = g_init + b * H_;
        else if (node >= 1 && node <= K_) p = g_upd + (b * K_ + (node - 1)) * H_;
        else                              p = g_zero;
        pN[t] = p;
        pE[t] = ent + (long)cents[rr] * E_;
        pR[t] = rel + (long)crels[rr] * E_;
    }
    if (t < 128) {
        s_state[t] = g_state[b * H_ + t];
        s_cb[t]    = cb[t];
    }
    __syncthreads();

    int aRow  = t >> 2, aC0 = (t & 3) * 8;
    int bRow0 = t >> 2, bRow1 = 64 + (t >> 2);
    uint32_t bSm0 = (uint32_t)(bRow0 * PITCH2 + aC0) * 2;
    uint32_t bSm1 = (uint32_t)(bRow1 * PITCH2 + aC0) * 2;

    uint32_t a_off = (uint32_t)((wm * 32 + (lane & 15)) * PITCH2 + ((lane >> 4) << 3)) * 2;
    uint32_t b_off = (uint32_t)((wn * 32 + (lane & 7) + ((lane >> 4) << 3)) * PITCH2
                                + (((lane >> 3) & 1) << 3)) * 2;
    const uint32_t STEP16 = (uint32_t)(16 * PITCH2) * 2;

    float acc[32];
    #pragma unroll
    for (int i = 0; i < 32; i++) acc[i] = 0.f;

    // tile 0
    {
        const float* src = pN[aRow] + aC0;
        uint4 a0 = cvt8_bf16(*(const float4*)src, *(const float4*)(src + 4));
        uint32_t bdst = smem_u32(Bs[0]);
        CP16(bdst + bSm0, g_cWb + bRow0 * 384 + aC0);
        CP16(bdst + bSm1, g_cWb + bRow1 * 384 + aC0);
        CPC();
        *(uint4*)(As[0] + aRow * PITCH2 + aC0) = a0;
        CPW0();
    }
    __syncthreads();

    uint4 aPf;
    #pragma unroll
    for (int j = 0; j < 12; j++) {
        int st = j & 1;
        if (j < 11) {
            int jn = j + 1;
            int seg = jn >> 2, kof = (jn & 3) * 32;
            const float* const* ptab = (seg == 0) ? pN : (seg == 1) ? pE : pR;
            const float* src = ptab[aRow] + kof + aC0;
            aPf = cvt8_bf16(*(const float4*)src, *(const float4*)(src + 4));
            uint32_t bdst = smem_u32(Bs[st ^ 1]);
            CP16(bdst + bSm0, g_cWb + bRow0 * 384 + jn * 32 + aC0);
            CP16(bdst + bSm1, g_cWb + bRow1 * 384 + jn * 32 + aC0);
            CPC();
        }
        uint32_t asb = smem_u32(As[st]), bsb = smem_u32(Bs[st]);
        #pragma unroll
        for (int ks = 0; ks < 2; ks++) {
            uint32_t kb = (uint32_t)(ks * 16) * 2;
            uint32_t a0[4], a1[4], b0[4], b1[4];
            ldm_x4(a0, asb + a_off + kb);
            ldm_x4(a1, asb + a_off + STEP16 + kb);
            ldm_x4(b0, bsb + b_off + kb);
            ldm_x4(b1, bsb + b_off + STEP16 + kb);
            mma16816(acc + 0,  a0, b0);  mma16816(acc + 4,  a0, b0 + 2);
            mma16816(acc + 8,  a0, b1);  mma16816(acc + 12, a0, b1 + 2);
            mma16816(acc + 16, a1, b0);  mma16816(acc + 20, a1, b0 + 2);
            mma16816(acc + 24, a1, b1);  mma16816(acc + 28, a1, b1 + 2);
        }
        if (j < 11) {
            *(uint4*)(As[st ^ 1] + aRow * PITCH2 + aC0) = aPf;
            CPW0();
            __syncthreads();
        }
    }

    // epilogue: lrelu+bias, dot(state), quad-reduce, cross-n-quarter reduce
    #pragma unroll
    for (int mi = 0; mi < 2; mi++) {
        float rl = 0.f, rh = 0.f;
        #pragma unroll
        for (int ni = 0; ni < 4; ni++) {
            int c0 = wn * 32 + ni * 8 + lp2, c1 = c0 + 1;
            const float* a = acc + mi * 16 + ni * 4;
            rl += lrelu(a[0] + s_cb[c0]) * s_state[c0] + lrelu(a[1] + s_cb[c1]) * s_state[c1];
            rh += lrelu(a[2] + s_cb[c0]) * s_state[c0] + lrelu(a[3] + s_cb[c1]) * s_state[c1];
        }
        rl += __shfl_xor_sync(0xFFFFFFFFu, rl, 1);
        rl += __shfl_xor_sync(0xFFFFFFFFu, rl, 2);
        rh += __shfl_xor_sync(0xFFFFFFFFu, rh, 1);
        rh += __shfl_xor_sync(0xFFFFFFFFu, rh, 2);
        if ((lane & 3) == 0) {
            sred[wn][wm * 32 + mi * 16 + l4]     = rl;
            sred[wn][wm * 32 + mi * 16 + l4 + 8] = rh;
        }
    }
    __syncthreads();

    if (t < 64) {
        float s = (sred[0][t] + sred[1][t] + sred[2][t] + sred[3][t])
                  * 0.08838834764831845f;          // 1/sqrt(128)
        int rr = rr0 + t;
        out[b * (MN_ + 1) + (rr & 255)] = cmask[rr] ? s : -100000.f;
    }
}

// ============================================================================
// launch
// ============================================================================
extern "C" void kernel_launch(void* const* d_in, const int* in_sizes, int n_in,
                              void* d_out, int out_size)
{
    const int*   start_entities      = (const int*)  d_in[0];
    const int*   aims                = (const int*)  d_in[1];
    /* node_pos = d_in[2]: arange(1..K), folded into indexing */
    const int*   neighbor_nodes      = (const int*)  d_in[3];
    const int*   neighbor_relations  = (const int*)  d_in[4];
    const int*   neighbors_num       = (const int*)  d_in[5];
    const int*   currents            = (const int*)  d_in[6];
    const int*   candidate_nodes     = (const int*)  d_in[7];
    const int*   candidate_entities  = (const int*)  d_in[8];
    const int*   candidate_relations = (const int*)  d_in[9];
    const int*   candidate_masks     = (const int*)  d_in[10];   // bool -> int32
    const float* entity_emb          = (const float*)d_in[11];
    const float* relation_emb        = (const float*)d_in[12];
    const float* hidden_W            = (const float*)d_in[13];
    const float* hidden_b            = (const float*)d_in[14];
    const float* pass_W              = (const float*)d_in[15];
    const float* pass_b              = (const float*)d_in[16];
    const float* nexthop_W           = (const float*)d_in[17];
    const float* nexthop_b           = (const float*)d_in[18];
    const float* candidate_W         = (const float*)d_in[19];
    const float* candidate_b         = (const float*)d_in[20];
    const float* gate_W              = (const float*)d_in[21];
    const float* gate_b              = (const float*)d_in[22];
    const float* query               = (const float*)d_in[23];
    float* out = (float*)d_out;

    ksetup   <<<4800, 256>>>(candidate_W, hidden_W, pass_W, nexthop_W,
                             start_entities, entity_emb, hidden_b,
                             neighbor_nodes, neighbor_relations, neighbors_num, relation_emb);
    k3_upd   <<<128, 256>>>(aims, entity_emb, hidden_b, pass_b,
                            currents, query, gate_W, gate_b, nexthop_b, out);
    k5_cand  <<<(B_ * MN_) / 64, 256>>>(candidate_nodes, candidate_entities,
                                        candidate_relations, candidate_masks,
                                        entity_emb, relation_emb, candidate_b, out);
}

// round 16
// speedup vs baseline: 1.3834x; 1.3834x over previous
#include <cuda_runtime.h>
#include <cuda_bf16.h>
#include <cstdint>

// ---------------- problem constants ----------------
#define B_   256
#define K_   32
#define M_   64
#define MN_  256
#define E_   128
#define H_   128
#define Q_   128
#define NR_  500

// ---------------- scratch (device globals) ----------------
__device__ float g_pnode [B_ * H_];
__device__ float g_c0d   [B_ * K_];
__device__ float g_cd    [B_ * K_];
__device__ float g_state [B_ * H_];
__device__ float g_nWT   [(H_ + Q_) * H_];        // nexthop_W transposed
__device__ float g_init  [B_ * H_];
__device__ float g_upd   [B_ * K_ * H_];
__device__ float g_relsum[B_ * K_ * E_];
__device__ float g_zero  [H_];                    // stays zero
__device__ __align__(16) __nv_bfloat16 g_cWb  [H_ * 384];     // candidate_W bf16
__device__ __align__(16) __nv_bfloat16 g_hpWb [H_ * 256];     // [hidden_W | pass_W[:,128:]] bf16

__device__ __forceinline__ float lrelu(float x) { return x >= 0.f ? x : 0.01f * x; }

__device__ __forceinline__ uint32_t smem_u32(const void* p) {
    uint32_t a;
    asm("{ .reg .u64 t; cvta.to.shared.u64 t, %1; cvt.u32.u64 %0, t; }" : "=r"(a) : "l"(p));
    return a;
}
__device__ __forceinline__ void mma16816(float* c, const uint32_t* a, const uint32_t* b) {
    asm volatile(
        "mma.sync.aligned.m16n8k16.row.col.f32.bf16.bf16.f32 "
        "{%0,%1,%2,%3}, {%4,%5,%6,%7}, {%8,%9}, {%0,%1,%2,%3};"
        : "+f"(c[0]), "+f"(c[1]), "+f"(c[2]), "+f"(c[3])
        : "r"(a[0]), "r"(a[1]), "r"(a[2]), "r"(a[3]), "r"(b[0]), "r"(b[1]));
}
__device__ __forceinline__ void ldm_x4(uint32_t* r, uint32_t addr) {
    asm volatile("ldmatrix.sync.aligned.m8n8.x4.shared.b16 {%0,%1,%2,%3}, [%4];"
        : "=r"(r[0]), "=r"(r[1]), "=r"(r[2]), "=r"(r[3]) : "r"(addr));
}
__device__ __forceinline__ uint4 cvt8_bf16(float4 va, float4 vb) {
    __nv_bfloat162 p0 = __floats2bfloat162_rn(va.x, va.y);
    __nv_bfloat162 p1 = __floats2bfloat162_rn(va.z, va.w);
    __nv_bfloat162 p2 = __floats2bfloat162_rn(vb.x, vb.y);
    __nv_bfloat162 p3 = __floats2bfloat162_rn(vb.z, vb.w);
    uint4 u;
    u.x = *(uint32_t*)&p0; u.y = *(uint32_t*)&p1;
    u.z = *(uint32_t*)&p2; u.w = *(uint32_t*)&p3;
    return u;
}
__device__ __forceinline__ float warp_dot_red(float d) {
    d += __shfl_xor_sync(0xFFFFFFFFu, d, 16);
    d += __shfl_xor_sync(0xFFFFFFFFu, d, 8);
    d += __shfl_xor_sync(0xFFFFFFFFu, d, 4);
    d += __shfl_xor_sync(0xFFFFFFFFu, d, 2);
    d += __shfl_xor_sync(0xFFFFFFFFu, d, 1);
    return d;
}
#define CP16(dst, src) \
    asm volatile("cp.async.cg.shared.global [%0], [%1], 16;" :: "r"(dst), "l"(src) : "memory")
#define CPC()  asm volatile("cp.async.commit_group;" ::: "memory")
#define CPW0() asm volatile("cp.async.wait_group 0;" ::: "memory")

#define PITCH2 40   // 32 bf16 + 8 pad: rows at 80B -> distinct banks for ldmatrix

// ============================================================================
// Setup: blocks [0,448) weight prep | [448,704) init/pnode (warp-coop) |
//        [704,4800) relsum
// ============================================================================
__global__ __launch_bounds__(256)
void ksetup(const float* __restrict__ cW, const float* __restrict__ hW,
            const float* __restrict__ pW, const float* __restrict__ nW,
            const int* __restrict__ start, const float* __restrict__ ent,
            const float* __restrict__ hb,
            const int* __restrict__ nb_nodes, const int* __restrict__ nb_rels,
            const int* __restrict__ nb_num, const float* __restrict__ rel_emb)
{
    int blk = blockIdx.x, t = threadIdx.x;

    if (blk < 448) {
        int i = blk * 256 + t;
        if (i < 49152) {
            g_cWb[i] = __float2bfloat16(cW[i]);
        } else if (i < 81920) {
            int j = i - 49152;
            int n = j >> 8, k = j & 255;
            g_hpWb[j] = __float2bfloat16(k < 128 ? hW[n * 128 + k] : pW[n * 256 + k]);
        } else {
            int m = i - 81920;
            int e = m >> 7, n = m & 127;
            g_nWT[m] = nW[n * 256 + e];
        }
        return;
    }

    if (blk < 704) {
        // ---- k1 (warp-cooperative): 8 warps x 16 n each ----
        int b = blk - 448;
        int wid = t >> 5, lane = t & 31;
        __shared__ float s_iv[H_];

        const float* xrow = ent + (long)start[b] * E_;
        float4 x4 = *(const float4*)(xrow + lane * 4);

        #pragma unroll
        for (int i = 0; i < 16; i++) {
            int n = wid * 16 + i;
            float4 h4 = *(const float4*)(hW + n * 128 + lane * 4);
            float d = h4.x * x4.x + h4.y * x4.y + h4.z * x4.z + h4.w * x4.w;
            d = warp_dot_red(d);
            if (lane == 0) {
                float v = lrelu(d + hb[n]);
                s_iv[n] = v;
                g_init[b * H_ + n] = v;
            }
        }
        __syncthreads();

        float4 i4 = *(const float4*)(s_iv + lane * 4);
        #pragma unroll
        for (int i = 0; i < 16; i++) {
            int n = wid * 16 + i;
            float4 p4 = *(const float4*)(pW + n * 256 + lane * 4);   // first 128 cols
            float d = p4.x * i4.x + p4.y * i4.y + p4.z * i4.z + p4.w * i4.w;
            d = warp_dot_red(d);
            if (lane == 0) g_pnode[b * H_ + n] = d;
        }
        return;
    }

    {
        __shared__ int s_rel[2][M_];
        __shared__ int s_c0[2];
        int sub = t >> 7, tt = t & 127;
        int r = (blk - 704) * 2 + sub;
        if (tt == 0) s_c0[sub] = 0;
        int cnt = nb_num[r];
        if (cnt < 0)  cnt = 0;
        if (cnt > M_) cnt = M_;
        if (tt < M_) s_rel[sub][tt] = nb_rels[r * M_ + tt];
        __syncthreads();
        if (tt < cnt && nb_nodes[r * M_ + tt] == 0) atomicAdd(&s_c0[sub], 1);

        float acc = 0.f;
        int m = 0;
        for (; m + 4 <= cnt; m += 4) {
            float v0 = rel_emb[s_rel[sub][m + 0] * E_ + tt];
            float v1 = rel_emb[s_rel[sub][m + 1] * E_ + tt];
            float v2 = rel_emb[s_rel[sub][m + 2] * E_ + tt];
            float v3 = rel_emb[s_rel[sub][m + 3] * E_ + tt];
            acc += (v0 + v1) + (v2 + v3);
        }
        for (; m < cnt; m++) acc += rel_emb[s_rel[sub][m] * E_ + tt];
        __syncthreads();

        float denom = (cnt == 0) ? 1.f : (float)cnt;
        g_relsum[r * E_ + tt] = acc / denom;
        if (tt == 0) {
            g_c0d[r] = (float)s_c0[sub] / denom;
            g_cd[r]  = (float)cnt / denom;
        }
    }
}

// ============================================================================
// Kernel 3 (warp-mma bf16, 32x32 warp tiles, cp.async B): upd GEMM
//   R=8192, N=128, K=256.  BM=64, grid(128), block(256) — R14-identical
// ============================================================================
__global__ __launch_bounds__(256)
void k3_upd(const int* __restrict__ aims, const float* __restrict__ ent,
            const float* __restrict__ hb, const float* __restrict__ pb)
{
    __shared__ __nv_bfloat16 As[2][64 * PITCH2];
    __shared__ __nv_bfloat16 Bs[2][128 * PITCH2];
    __shared__ const float* rowp[64];
    __shared__ float s_c0d[64], s_cd[64], s_hb[128], s_pb[128], s_pn[2 * 128];

    int t    = threadIdx.x;
    int wid  = t >> 5, lane = t & 31;
    int l4   = lane >> 2, lp2 = (lane & 3) * 2;
    int wm   = wid & 1, wn = wid >> 1;
    int rr0  = blockIdx.x * 64;
    int b0   = rr0 >> 5;

    if (t < 64) {
        int rr = rr0 + t;
        rowp[t]  = ent + (long)aims[rr] * E_;
        s_c0d[t] = g_c0d[rr];
        s_cd[t]  = g_cd[rr];
    }
    if (t < 128) {
        s_hb[t] = hb[t];
        s_pb[t] = pb[t];
        s_pn[t] = g_pnode[b0 * H_ + t];
        s_pn[128 + t] = g_pnode[(b0 + 1) * H_ + t];
    }
    __syncthreads();

    int aRow  = t >> 2, aC0 = (t & 3) * 8;
    int bRow0 = t >> 2, bRow1 = 64 + (t >> 2);
    uint32_t bSm0 = (uint32_t)(bRow0 * PITCH2 + aC0) * 2;
    uint32_t bSm1 = (uint32_t)(bRow1 * PITCH2 + aC0) * 2;

    uint32_t a_off = (uint32_t)((wm * 32 + (lane & 15)) * PITCH2 + ((lane >> 4) << 3)) * 2;
    uint32_t b_off = (uint32_t)((wn * 32 + (lane & 7) + ((lane >> 4) << 3)) * PITCH2
                                + (((lane >> 3) & 1) << 3)) * 2;
    const uint32_t STEP16 = (uint32_t)(16 * PITCH2) * 2;

    float acc[32];
    #pragma unroll
    for (int i = 0; i < 32; i++) acc[i] = 0.f;

    // tile 0: A via regs, B via cp.async
    {
        const float* src = rowp[aRow] + aC0;
        uint4 a0 = cvt8_bf16(*(const float4*)src, *(const float4*)(src + 4));
        uint32_t bdst = smem_u32(Bs[0]);
        CP16(bdst + bSm0, g_hpWb + bRow0 * 256 + aC0);
        CP16(bdst + bSm1, g_hpWb + bRow1 * 256 + aC0);
        CPC();
        *(uint4*)(As[0] + aRow * PITCH2 + aC0) = a0;
        CPW0();
    }
    __syncthreads();

    uint4 aPf;
    #pragma unroll
    for (int j = 0; j < 8; j++) {
        int st = j & 1;
        if (j < 7) {
            int jn = j + 1;
            int kof = (jn & 3) * 32;
            const float* src = (jn < 4) ? (rowp[aRow] + kof + aC0)
                                        : (g_relsum + (rr0 + aRow) * E_ + kof + aC0);
            aPf = cvt8_bf16(*(const float4*)src, *(const float4*)(src + 4));
            uint32_t bdst = smem_u32(Bs[st ^ 1]);
            CP16(bdst + bSm0, g_hpWb + bRow0 * 256 + jn * 32 + aC0);
            CP16(bdst + bSm1, g_hpWb + bRow1 * 256 + jn * 32 + aC0);
            CPC();
        }
        uint32_t asb = smem_u32(As[st]), bsb = smem_u32(Bs[st]);
        #pragma unroll
        for (int ks = 0; ks < 2; ks++) {
            uint32_t kb = (uint32_t)(ks * 16) * 2;
            uint32_t a0[4], a1[4], b0[4], b1[4];
            ldm_x4(a0, asb + a_off + kb);
            ldm_x4(a1, asb + a_off + STEP16 + kb);
            ldm_x4(b0, bsb + b_off + kb);
            ldm_x4(b1, bsb + b_off + STEP16 + kb);
            mma16816(acc + 0,  a0, b0);  mma16816(acc + 4,  a0, b0 + 2);
            mma16816(acc + 8,  a0, b1);  mma16816(acc + 12, a0, b1 + 2);
            mma16816(acc + 16, a1, b0);  mma16816(acc + 20, a1, b0 + 2);
            mma16816(acc + 24, a1, b1);  mma16816(acc + 28, a1, b1 + 2);
        }
        if (j < 7) {
            *(uint4*)(As[st ^ 1] + aRow * PITCH2 + aC0) = aPf;
            CPW0();
            __syncthreads();
        }
    }

    // epilogue -> g_upd
    #pragma unroll
    for (int mi = 0; mi < 2; mi++) {
        int rl0 = wm * 32 + mi * 16 + l4, rl1 = rl0 + 8;
        int bi0 = (rl0 >> 5) * 128, bi1 = (rl1 >> 5) * 128;
        #pragma unroll
        for (int ni = 0; ni < 4; ni++) {
            int c0 = wn * 32 + ni * 8 + lp2, c1 = c0 + 1;
            const float* a = acc + mi * 16 + ni * 4;
            g_upd[(rr0 + rl0) * H_ + c0] =
                lrelu(a[0] + s_hb[c0] + s_c0d[rl0] * s_pn[bi0 + c0] + s_cd[rl0] * s_pb[c0]);
            g_upd[(rr0 + rl0) * H_ + c1] =
                lrelu(a[1] + s_hb[c1] + s_c0d[rl0] * s_pn[bi0 + c1] + s_cd[rl0] * s_pb[c1]);
            g_upd[(rr0 + rl1) * H_ + c0] =
                lrelu(a[2] + s_hb[c0] + s_c0d[rl1] * s_pn[bi1 + c0] + s_cd[rl1] * s_pb[c0]);
            g_upd[(rr0 + rl1) * H_ + c1] =
                lrelu(a[3] + s_hb[c1] + s_c0d[rl1] * s_pn[bi1 + c1] + s_cd[rl1] * s_pb[c1]);
        }
    }
}

// ============================================================================
// Kernel 4 (4-way e-split, R14-identical): cc=[cur;query]; gate; state matvec
// ============================================================================
__global__ __launch_bounds__(512)
void k4_state(const int* __restrict__ currents, const float* __restrict__ query,
              const float* __restrict__ gW, const float* __restrict__ gb,
              const float* __restrict__ nbias, float* __restrict__ out)
{
    int b = blockIdx.x, t = threadIdx.x;
    __shared__ float cc[256];
    __shared__ float part[4][128];
    __shared__ float red[128];

    if (t < 128) {
        int c = currents[b];
        float cur;
        if (c == 0)                 cur = g_init[b * H_ + t];
        else if (c >= 1 && c <= K_) cur = g_upd[(b * K_ + (c - 1)) * H_ + t];
        else                        cur = 0.f;
        float q = query[b * Q_ + t];
        cc[t]       = cur;
        cc[128 + t] = q;
        red[t] = gW[t] * cur + gW[128 + t] * q;
    }
    __syncthreads();
    for (int s = 64; s > 0; s >>= 1) {
        if (t < s) red[t] += red[t + s];
        __syncthreads();
    }
    if (t == 0) out[b * (MN_ + 1) + MN_] = red[0] + gb[0];

    int n = t & 127, seg = t >> 7;
    const float* w = g_nWT + (seg * 64) * 128 + n;
    float acc = 0.f;
    #pragma unroll 8
    for (int e = 0; e < 64; e++) acc += cc[seg * 64 + e] * w[e * 128];
    part[seg][n] = acc;
    __syncthreads();

    if (t < 128) {
        float s = part[0][t] + part[1][t] + part[2][t] + part[3][t];
        g_state[b * H_ + t] = lrelu(s + nbias[t]);
    }
}

// ============================================================================
// Kernel 5 (warp-mma bf16, 32x32 warp tiles, cp.async B): candidate GEMM
//   R=65536, N=128, K=384.  BM=64, grid(1024), block(256) — R14-identical
// ============================================================================
__global__ __launch_bounds__(256)
void k5_cand(const int* __restrict__ cnodes, const int* __restrict__ cents,
             const int* __restrict__ crels, const int* __restrict__ cmask,
             const float* __restrict__ ent, const float* __restrict__ rel,
             const float* __restrict__ cb, float* __restrict__ out)
{
    __shared__ __nv_bfloat16 As[2][64 * PITCH2];
    __shared__ __nv_bfloat16 Bs[2][128 * PITCH2];
    __shared__ const float* pN[64];
    __shared__ const float* pE[64];
    __shared__ const float* pR[64];
    __shared__ float s_state[H_], s_cb[H_];
    __shared__ float sred[4][64];

    int t    = threadIdx.x;
    int wid  = t >> 5, lane = t & 31;
    int l4   = lane >> 2, lp2 = (lane & 3) * 2;
    int wm   = wid & 1, wn = wid >> 1;
    int rr0  = blockIdx.x * 64;
    int b    = rr0 >> 8;

    if (t < 64) {
        int rr = rr0 + t;
        int node = cnodes[rr];
        const float* p;
        if (node == 0)                    p = g_init + b * H_;
        else if (node >= 1 && node <= K_) p = g_upd + (b * K_ + (node - 1)) * H_;
        else                              p = g_zero;
        pN[t] = p;
        pE[t] = ent + (long)cents[rr] * E_;
        pR[t] = rel + (long)crels[rr] * E_;
    }
    if (t < 128) {
        s_state[t] = g_state[b * H_ + t];
        s_cb[t]    = cb[t];
    }
    __syncthreads();

    int aRow  = t >> 2, aC0 = (t & 3) * 8;
    int bRow0 = t >> 2, bRow1 = 64 + (t >> 2);
    uint32_t bSm0 = (uint32_t)(bRow0 * PITCH2 + aC0) * 2;
    uint32_t bSm1 = (uint32_t)(bRow1 * PITCH2 + aC0) * 2;

    uint32_t a_off = (uint32_t)((wm * 32 + (lane & 15)) * PITCH2 + ((lane >> 4) << 3)) * 2;
    uint32_t b_off = (uint32_t)((wn * 32 + (lane & 7) + ((lane >> 4) << 3)) * PITCH2
                                + (((lane >> 3) & 1) << 3)) * 2;
    const uint32_t STEP16 = (uint32_t)(16 * PITCH2) * 2;

    float acc[32];
    #pragma unroll
    for (int i = 0; i < 32; i++) acc[i] = 0.f;

    // tile 0
    {
        const float* src = pN[aRow] + aC0;
        uint4 a0 = cvt8_bf16(*(const float4*)src, *(const float4*)(src + 4));
        uint32_t bdst = smem_u32(Bs[0]);
        CP16(bdst + bSm0, g_cWb + bRow0 * 384 + aC0);
        CP16(bdst + bSm1, g_cWb + bRow1 * 384 + aC0);
        CPC();
        *(uint4*)(As[0] + aRow * PITCH2 + aC0) = a0;
        CPW0();
    }
    __syncthreads();

    uint4 aPf;
    #pragma unroll
    for (int j = 0; j < 12; j++) {
        int st = j & 1;
        if (j < 11) {
            int jn = j + 1;
            int seg = jn >> 2, kof = (jn & 3) * 32;
            const float* const* ptab = (seg == 0) ? pN : (seg == 1) ? pE : pR;
            const float* src = ptab[aRow] + kof + aC0;
            aPf = cvt8_bf16(*(const float4*)src, *(const float4*)(src + 4));
            uint32_t bdst = smem_u32(Bs[st ^ 1]);
            CP16(bdst + bSm0, g_cWb + bRow0 * 384 + jn * 32 + aC0);
            CP16(bdst + bSm1, g_cWb + bRow1 * 384 + jn * 32 + aC0);
            CPC();
        }
        uint32_t asb = smem_u32(As[st]), bsb = smem_u32(Bs[st]);
        #pragma unroll
        for (int ks = 0; ks < 2; ks++) {
            uint32_t kb = (uint32_t)(ks * 16) * 2;
            uint32_t a0[4], a1[4], b0[4], b1[4];
            ldm_x4(a0, asb + a_off + kb);
            ldm_x4(a1, asb + a_off + STEP16 + kb);
            ldm_x4(b0, bsb + b_off + kb);
            ldm_x4(b1, bsb + b_off + STEP16 + kb);
            mma16816(acc + 0,  a0, b0);  mma16816(acc + 4,  a0, b0 + 2);
            mma16816(acc + 8,  a0, b1);  mma16816(acc + 12, a0, b1 + 2);
            mma16816(acc + 16, a1, b0);  mma16816(acc + 20, a1, b0 + 2);
            mma16816(acc + 24, a1, b1);  mma16816(acc + 28, a1, b1 + 2);
        }
        if (j < 11) {
            *(uint4*)(As[st ^ 1] + aRow * PITCH2 + aC0) = aPf;
            CPW0();
            __syncthreads();
        }
    }

    // epilogue: lrelu+bias, dot(state), quad-reduce, cross-n-quarter reduce
    #pragma unroll
    for (int mi = 0; mi < 2; mi++) {
        float rl = 0.f, rh = 0.f;
        #pragma unroll
        for (int ni = 0; ni < 4; ni++) {
            int c0 = wn * 32 + ni * 8 + lp2, c1 = c0 + 1;
            const float* a = acc + mi * 16 + ni * 4;
            rl += lrelu(a[0] + s_cb[c0]) * s_state[c0] + lrelu(a[1] + s_cb[c1]) * s_state[c1];
            rh += lrelu(a[2] + s_cb[c0]) * s_state[c0] + lrelu(a[3] + s_cb[c1]) * s_state[c1];
        }
        rl += __shfl_xor_sync(0xFFFFFFFFu, rl, 1);
        rl += __shfl_xor_sync(0xFFFFFFFFu, rl, 2);
        rh += __shfl_xor_sync(0xFFFFFFFFu, rh, 1);
        rh += __shfl_xor_sync(0xFFFFFFFFu, rh, 2);
        if ((lane & 3) == 0) {
            sred[wn][wm * 32 + mi * 16 + l4]     = rl;
            sred[wn][wm * 32 + mi * 16 + l4 + 8] = rh;
        }
    }
    __syncthreads();

    if (t < 64) {
        float s = (sred[0][t] + sred[1][t] + sred[2][t] + sred[3][t])
                  * 0.08838834764831845f;          // 1/sqrt(128)
        int rr = rr0 + t;
        out[b * (MN_ + 1) + (rr & 255)] = cmask[rr] ? s : -100000.f;
    }
}

// ============================================================================
// launch
// ============================================================================
extern "C" void kernel_launch(void* const* d_in, const int* in_sizes, int n_in,
                              void* d_out, int out_size)
{
    const int*   start_entities      = (const int*)  d_in[0];
    const int*   aims                = (const int*)  d_in[1];
    /* node_pos = d_in[2]: arange(1..K), folded into indexing */
    const int*   neighbor_nodes      = (const int*)  d_in[3];
    const int*   neighbor_relations  = (const int*)  d_in[4];
    const int*   neighbors_num       = (const int*)  d_in[5];
    const int*   currents            = (const int*)  d_in[6];
    const int*   candidate_nodes     = (const int*)  d_in[7];
    const int*   candidate_entities  = (const int*)  d_in[8];
    const int*   candidate_relations = (const int*)  d_in[9];
    const int*   candidate_masks     = (const int*)  d_in[10];   // bool -> int32
    const float* entity_emb          = (const float*)d_in[11];
    const float* relation_emb        = (const float*)d_in[12];
    const float* hidden_W            = (const float*)d_in[13];
    const float* hidden_b            = (const float*)d_in[14];
    const float* pass_W              = (const float*)d_in[15];
    const float* pass_b              = (const float*)d_in[16];
    const float* nexthop_W           = (const float*)d_in[17];
    const float* nexthop_b           = (const float*)d_in[18];
    const float* candidate_W         = (const float*)d_in[19];
    const float* candidate_b         = (const float*)d_in[20];
    const float* gate_W              = (const float*)d_in[21];
    const float* gate_b              = (const float*)d_in[22];
    const float* query               = (const float*)d_in[23];
    float* out = (float*)d_out;

    ksetup   <<<4800, 256>>>(candidate_W, hidden_W, pass_W, nexthop_W,
                             start_entities, entity_emb, hidden_b,
                             neighbor_nodes, neighbor_relations, neighbors_num, relation_emb);
    k3_upd   <<<128, 256>>>(aims, entity_emb, hidden_b, pass_b);
    k4_state <<<B_, 512>>>(currents, query, gate_W, gate_b, nexthop_b, out);
    k5_cand  <<<(B_ * MN_) / 64, 256>>>(candidate_nodes, candidate_entities,
                                        candidate_relations, candidate_masks,
                                        entity_emb, relation_emb, candidate_b, out);
}